// round 11
// baseline (speedup 1.0000x reference)
#include <cuda_runtime.h>
#include <cuda_bf16.h>
#include <cuda_fp16.h>
#include <mma.h>

#define N_NODES 100000
#define D 128
#define N_EDGES 1600000
#define BATCH 500000
#define LN_EPS 1e-5f
#define SCAN_CHUNK 1024
#define NBLK ((N_NODES + SCAN_CHUNK - 1) / SCAN_CHUNK)   // 98
#define HB 148                                           // persistent hist blocks
#define GEMM_BLOCKS ((N_NODES + 63) / 64)                // 1563

using namespace nvcuda;

// Scratch (device globals; no allocation allowed)
__device__ __align__(128) __half g_h1h[N_NODES * D]; // GEMM output (fp16)
__device__ __align__(128) int2  g_epack[N_EDGES];    // CSR-permuted {col, val}
__device__ int g_eloc[N_EDGES];
__device__ int g_elocb[BATCH];
__device__ int g_bidx[BATCH];                        // batch ids grouped by node
__device__ int g_cnt[N_NODES];
__device__ int g_cntb[N_NODES];
__device__ int g_rowptr[N_NODES + 1];
__device__ int g_rowptrb[N_NODES + 1];
__device__ int g_bsumA[NBLK];
__device__ int g_bsumB[NBLK];
__device__ __align__(128) __nv_bfloat16 g_Wh[D * D];
__device__ __align__(128) __nv_bfloat16 g_Wl[D * D];

#define LDA 136
#define LDC 132

// ---------------- init: W hi/lo pre-conversion + zero both histograms ----------------
__global__ void init_kernel(const float* __restrict__ W) {
    int i = blockIdx.x * blockDim.x + threadIdx.x;
    if (i < D * D) {
        float wv = W[i];
        __nv_bfloat16 whi = __float2bfloat16(wv);
        g_Wh[i] = whi;
        g_Wl[i] = __float2bfloat16(wv - __bfloat162float(whi));
    }
    if (i < N_NODES) { g_cnt[i] = 0; g_cntb[i] = 0; }
}

// ---------------- fused GEMM + dual histogram ----------------
// Blocks [0, HB): persistent grid-stride histogram over edges+batch (LTS-bound).
// Blocks [HB, HB+GEMM_BLOCKS): one 64-row GEMM tile each (tensor/L1-bound).
// W fragments are read straight from global (L1-resident) -> smem is A-only (35KB).
__global__ void gemm_hist_kernel(const float* __restrict__ emb,
                                 const float* __restrict__ bias,
                                 const int* __restrict__ rows,
                                 const int* __restrict__ x) {
    __shared__ __nv_bfloat16 smem[2 * 64 * LDA];   // 34816 bytes

    if (blockIdx.x < HB) {
        // ---- histogram part ----
        const int TOT = N_EDGES + BATCH;
        const int T = HB * 256;
        int base = blockIdx.x * 256 + threadIdx.x;
        for (int i0 = base; i0 < TOT; i0 += T * 4) {
            #pragma unroll
            for (int u = 0; u < 4; u++) {
                int i = i0 + u * T;
                if (i < N_EDGES) {
                    g_eloc[i] = atomicAdd(&g_cnt[rows[i]], 1);
                } else if (i < TOT) {
                    int b = i - N_EDGES;
                    int xv = x[b];
                    if (xv >= 1 && xv <= N_NODES)
                        g_elocb[b] = atomicAdd(&g_cntb[xv - 1], 1);
                    else
                        g_elocb[b] = -1;
                }
            }
        }
        return;
    }

    // ---- GEMM part ----
    __nv_bfloat16* sAh = smem;
    __nv_bfloat16* sAl = sAh + 64 * LDA;
    float* sC = (float*)smem;      // reuse after MMA (64*132*4 = 33792 <= 34816)

    int tid = threadIdx.x;
    int wid = tid >> 5;
    int wr = wid >> 1;
    int wc = wid & 1;
    int block_row = (blockIdx.x - HB) * 64;

    for (int i = tid; i < 64 * 32; i += 256) {
        int r = i >> 5, c4 = i & 31;
        int grow = block_row + r;
        float4 a = make_float4(0.f, 0.f, 0.f, 0.f);
        if (grow < N_NODES) a = ((const float4*)(emb + (size_t)grow * D))[c4];
        __nv_bfloat16 h0 = __float2bfloat16(a.x), h1 = __float2bfloat16(a.y);
        __nv_bfloat16 h2 = __float2bfloat16(a.z), h3 = __float2bfloat16(a.w);
        __nv_bfloat16 l0 = __float2bfloat16(a.x - __bfloat162float(h0));
        __nv_bfloat16 l1 = __float2bfloat16(a.y - __bfloat162float(h1));
        __nv_bfloat16 l2 = __float2bfloat16(a.z - __bfloat162float(h2));
        __nv_bfloat16 l3 = __float2bfloat16(a.w - __bfloat162float(h3));
        __nv_bfloat162* ph = (__nv_bfloat162*)(sAh + r * LDA);
        __nv_bfloat162* pl = (__nv_bfloat162*)(sAl + r * LDA);
        ph[c4 * 2]     = __nv_bfloat162(h0, h1);
        ph[c4 * 2 + 1] = __nv_bfloat162(h2, h3);
        pl[c4 * 2]     = __nv_bfloat162(l0, l1);
        pl[c4 * 2 + 1] = __nv_bfloat162(l2, l3);
    }
    __syncthreads();

    wmma::fragment<wmma::accumulator, 16, 16, 16, float> acc[4];
    #pragma unroll
    for (int c = 0; c < 4; c++) wmma::fill_fragment(acc[c], 0.f);

    #pragma unroll
    for (int k = 0; k < 8; k++) {
        wmma::fragment<wmma::matrix_a, 16, 16, 16, __nv_bfloat16, wmma::row_major> ah, al;
        wmma::load_matrix_sync(ah, sAh + wr * 16 * LDA + k * 16, LDA);
        wmma::load_matrix_sync(al, sAl + wr * 16 * LDA + k * 16, LDA);
        #pragma unroll
        for (int c = 0; c < 4; c++) {
            int cc = wc * 64 + c * 16;
            wmma::fragment<wmma::matrix_b, 16, 16, 16, __nv_bfloat16, wmma::row_major> bh, bl;
            wmma::load_matrix_sync(bh, g_Wh + k * 16 * D + cc, D);   // global, L1-hot
            wmma::load_matrix_sync(bl, g_Wl + k * 16 * D + cc, D);
            wmma::mma_sync(acc[c], ah, bh, acc[c]);
            wmma::mma_sync(acc[c], ah, bl, acc[c]);
            wmma::mma_sync(acc[c], al, bh, acc[c]);
        }
    }
    __syncthreads();
    #pragma unroll
    for (int c = 0; c < 4; c++)
        wmma::store_matrix_sync(sC + wr * 16 * LDC + wc * 64 + c * 16, acc[c],
                                LDC, wmma::mem_row_major);
    __syncthreads();

    for (int i = tid; i < 64 * 32; i += 256) {
        int r = i >> 5, c4 = i & 31;
        int grow = block_row + r;
        if (grow < N_NODES) {
            float4 cv = ((const float4*)(sC + r * LDC))[c4];
            float4 bv = ((const float4*)bias)[c4];
            __half2* p = (__half2*)(g_h1h + (size_t)grow * D);
            p[c4 * 2]     = __floats2half2_rn(cv.x + bv.x, cv.y + bv.y);
            p[c4 * 2 + 1] = __floats2half2_rn(cv.z + bv.z, cv.w + bv.w);
        }
    }
}

// ---------------- scans ----------------
// per-1024-chunk inclusive scan; blockIdx.y selects {edges, batch}
__global__ void scanA_kernel() {
    __shared__ int ws[32];
    int a = blockIdx.y;
    const int* cnt = a ? g_cntb : g_cnt;
    int* rp = a ? g_rowptrb : g_rowptr;
    int* bs = a ? g_bsumB : g_bsumA;
    int tid = threadIdx.x;
    int lane = tid & 31, w = tid >> 5;
    int idx = blockIdx.x * SCAN_CHUNK + tid;
    int v = (idx < N_NODES) ? cnt[idx] : 0;
    int inc = v;
    #pragma unroll
    for (int off = 1; off < 32; off <<= 1) {
        int t = __shfl_up_sync(0xffffffffu, inc, off);
        if (lane >= off) inc += t;
    }
    if (lane == 31) ws[w] = inc;
    __syncthreads();
    if (w == 0) {
        int b = ws[lane];
        #pragma unroll
        for (int off = 1; off < 32; off <<= 1) {
            int t = __shfl_up_sync(0xffffffffu, b, off);
            if (lane >= off) b += t;
        }
        ws[lane] = b;
    }
    __syncthreads();
    int total = inc + (w ? ws[w - 1] : 0);
    if (idx < N_NODES) rp[idx + 1] = total;
    if (tid == SCAN_CHUNK - 1) bs[blockIdx.x] = total;
}

// fused scanB+C: each block reduces the block sums before it, then offsets its chunk
__global__ void scanC_kernel() {
    int a = blockIdx.y;
    int* rp = a ? g_rowptrb : g_rowptr;
    const int* bs = a ? g_bsumB : g_bsumA;
    __shared__ int sacc;
    if (threadIdx.x == 0) sacc = 0;
    __syncthreads();
    int v = (threadIdx.x < blockIdx.x) ? bs[threadIdx.x] : 0;   // blockIdx.x <= 97 < NBLK
    #pragma unroll
    for (int off = 16; off; off >>= 1) v += __shfl_xor_sync(0xffffffffu, v, off);
    if ((threadIdx.x & 31) == 0 && v) atomicAdd(&sacc, v);
    __syncthreads();
    int add = sacc;
    int idx = blockIdx.x * SCAN_CHUNK + threadIdx.x;
    if (idx < N_NODES) rp[idx + 1] += add;
    if (idx == 0) rp[0] = 0;
}

// ---------------- fused scatter: edges + batch ids (+ zero invalid out rows) ----------
__global__ void scatter_kernel(const float* __restrict__ vals,
                               const int* __restrict__ rows,
                               const int* __restrict__ cols,
                               const int* __restrict__ x,
                               float* __restrict__ out) {
    int i = blockIdx.x * blockDim.x + threadIdx.x;
    if (i < N_EDGES) {
        int p = g_rowptr[rows[i]] + g_eloc[i];
        g_epack[p] = make_int2(cols[i], __float_as_int(vals[i]));
    }
    int b = i - N_EDGES;
    if (b >= 0 && b < BATCH) {
        int xv = x[b];
        if (xv >= 1 && xv <= N_NODES) {
            g_bidx[g_rowptrb[xv - 1] + g_elocb[b]] = b;
        } else {
            float4* o = (float4*)(out + (size_t)b * D);
            #pragma unroll
            for (int k = 0; k < 32; k++) o[k] = make_float4(0.f, 0.f, 0.f, 0.f);
        }
    }
}

// ---------------- fused SpMM + ReLU + LayerNorm + direct batch scatter ----------------
__global__ void spmm_ln_kernel(const float* __restrict__ gamma,
                               const float* __restrict__ beta,
                               float* __restrict__ out) {
    int row = blockIdx.x * 8 + (threadIdx.x >> 5);
    if (row >= N_NODES) return;
    int lane = threadIdx.x & 31;
    int s = g_rowptr[row];
    int e = g_rowptr[row + 1];

    float4 acc = make_float4(0.f, 0.f, 0.f, 0.f);
    for (int base = s; base < e; base += 32) {
        int n = min(32, e - base);
        int2 ev = make_int2(0, 0);
        if (base + lane < e) ev = g_epack[base + lane];
        int j = 0;
        for (; j + 8 <= n; j += 8) {
            float v[8]; uint2 m[8];
            #pragma unroll
            for (int u = 0; u < 8; u++) {
                int c = __shfl_sync(0xffffffffu, ev.x, j + u);
                v[u] = __int_as_float(__shfl_sync(0xffffffffu, ev.y, j + u));
                m[u] = ((const uint2*)(g_h1h + (size_t)c * D))[lane];
            }
            #pragma unroll
            for (int u = 0; u < 8; u++) {
                float2 f0 = __half22float2(*(__half2*)&m[u].x);
                float2 f1 = __half22float2(*(__half2*)&m[u].y);
                acc.x = fmaf(v[u], f0.x, acc.x);
                acc.y = fmaf(v[u], f0.y, acc.y);
                acc.z = fmaf(v[u], f1.x, acc.z);
                acc.w = fmaf(v[u], f1.y, acc.w);
            }
        }
        for (; j < n; j++) {
            int   c = __shfl_sync(0xffffffffu, ev.x, j);
            float v = __int_as_float(__shfl_sync(0xffffffffu, ev.y, j));
            uint2 m = ((const uint2*)(g_h1h + (size_t)c * D))[lane];
            float2 f0 = __half22float2(*(__half2*)&m.x);
            float2 f1 = __half22float2(*(__half2*)&m.y);
            acc.x = fmaf(v, f0.x, acc.x);
            acc.y = fmaf(v, f0.y, acc.y);
            acc.z = fmaf(v, f1.x, acc.z);
            acc.w = fmaf(v, f1.y, acc.w);
        }
    }

    acc.x = fmaxf(acc.x, 0.f); acc.y = fmaxf(acc.y, 0.f);
    acc.z = fmaxf(acc.z, 0.f); acc.w = fmaxf(acc.w, 0.f);

    float sm = acc.x + acc.y + acc.z + acc.w;
    #pragma unroll
    for (int o = 16; o; o >>= 1) sm += __shfl_xor_sync(0xffffffffu, sm, o);
    float mu = sm * (1.f / 128.f);

    float dx = acc.x - mu, dy = acc.y - mu, dz = acc.z - mu, dw = acc.w - mu;
    float q = dx * dx + dy * dy + dz * dz + dw * dw;
    #pragma unroll
    for (int o = 16; o; o >>= 1) q += __shfl_xor_sync(0xffffffffu, q, o);
    float rs = rsqrtf(q * (1.f / 128.f) + LN_EPS);

    float4 g = ((const float4*)gamma)[lane];
    float4 b = ((const float4*)beta)[lane];
    float4 o;
    o.x = dx * rs * g.x + b.x;
    o.y = dy * rs * g.y + b.y;
    o.z = dz * rs * g.z + b.z;
    o.w = dw * rs * g.w + b.w;

    int sb = g_rowptrb[row];
    int eb = g_rowptrb[row + 1];
    for (int t = sb; t < eb; t++) {
        int b2 = g_bidx[t];
        __stcs((float4*)(out + (size_t)b2 * D) + lane, o);
    }
}

extern "C" void kernel_launch(void* const* d_in, const int* in_sizes, int n_in,
                              void* d_out, int out_size) {
    const int*   x     = (const int*)d_in[0];
    const float* emb   = (const float*)d_in[1];
    const float* W     = (const float*)d_in[2];
    const float* bias  = (const float*)d_in[3];
    const float* vals  = (const float*)d_in[4];
    const int*   rows  = (const int*)d_in[5];
    const int*   cols  = (const int*)d_in[6];
    const float* gamma = (const float*)d_in[7];
    const float* beta  = (const float*)d_in[8];
    float* out = (float*)d_out;

    init_kernel<<<(N_NODES + 255) / 256, 256>>>(W);
    gemm_hist_kernel<<<HB + GEMM_BLOCKS, 256>>>(emb, bias, rows, x);
    scanA_kernel<<<dim3(NBLK, 2), SCAN_CHUNK>>>();
    scanC_kernel<<<dim3(NBLK, 2), SCAN_CHUNK>>>();
    scatter_kernel<<<(N_EDGES + BATCH + 255) / 256, 256>>>(vals, rows, cols, x, out);
    spmm_ln_kernel<<<(N_NODES + 7) / 8, 256>>>(gamma, beta, out);
}

// round 12
// speedup vs baseline: 1.1356x; 1.1356x over previous
#include <cuda_runtime.h>
#include <cuda_bf16.h>
#include <cuda_fp16.h>
#include <mma.h>

#define N_NODES 100000
#define D 128
#define N_EDGES 1600000
#define BATCH 500000
#define LN_EPS 1e-5f
#define SCAN_CHUNK 1024
#define NBLK ((N_NODES + SCAN_CHUNK - 1) / SCAN_CHUNK)   // 98

using namespace nvcuda;

// Scratch (device globals; no allocation allowed)
__device__ __align__(128) __half g_h1h[N_NODES * D]; // GEMM output (fp16)
__device__ __align__(128) int2  g_epack[N_EDGES];    // CSR-permuted {col, val}
__device__ int g_eloc[N_EDGES];
__device__ int g_elocb[BATCH];
__device__ int g_bidx[BATCH];                        // batch ids grouped by node
__device__ int g_cnt[N_NODES];
__device__ int g_cntb[N_NODES];
__device__ int g_rowptr[N_NODES + 1];
__device__ int g_rowptrb[N_NODES + 1];
__device__ int g_bsumA[NBLK];
__device__ int g_bsumB[NBLK];
__device__ __align__(128) __nv_bfloat16 g_Wh[D * D];
__device__ __align__(128) __nv_bfloat16 g_Wl[D * D];

#define LDA 136
#define LDB 136
#define LDC 132
#define BLK_ROWS 64
#define GEMM_SMEM (128 * LDB * 2 * 2 + BLK_ROWS * LDA * 2 * 2)   // 104448

// ---------------- init: W hi/lo pre-conversion + zero both histograms ----------------
__global__ void init_kernel(const float* __restrict__ W) {
    int i = blockIdx.x * blockDim.x + threadIdx.x;
    if (i < D * D) {
        float wv = W[i];
        __nv_bfloat16 whi = __float2bfloat16(wv);
        g_Wh[i] = whi;
        g_Wl[i] = __float2bfloat16(wv - __bfloat162float(whi));
    }
    if (i < N_NODES) { g_cnt[i] = 0; g_cntb[i] = 0; }
}

// ---------------- GEMM: h1 = emb @ W + bias (bf16 hi/lo, fp32 accum, fp16 store) ------
// R10 version: W staged in smem via vectorized copy (load-bearing; do not remove).
__global__ void gemm_kernel(const float* __restrict__ emb,
                            const float* __restrict__ bias) {
    extern __shared__ __nv_bfloat16 smem[];
    __nv_bfloat16* sWh = smem;
    __nv_bfloat16* sWl = sWh + 128 * LDB;
    __nv_bfloat16* sAh = sWl + 128 * LDB;
    __nv_bfloat16* sAl = sAh + BLK_ROWS * LDA;
    float* sC = (float*)sAh;

    int tid = threadIdx.x;
    int wid = tid >> 5;
    int wr = wid >> 1;
    int wc = wid & 1;
    int block_row = blockIdx.x * BLK_ROWS;

    for (int i = tid; i < 128 * 16; i += 256) {
        int r = i >> 4, q = i & 15;
        ((uint4*)(sWh + r * LDB))[q] = ((const uint4*)(g_Wh + r * D))[q];
        ((uint4*)(sWl + r * LDB))[q] = ((const uint4*)(g_Wl + r * D))[q];
    }
    for (int i = tid; i < BLK_ROWS * 32; i += 256) {
        int r = i >> 5, c4 = i & 31;
        int grow = block_row + r;
        float4 a = make_float4(0.f, 0.f, 0.f, 0.f);
        if (grow < N_NODES) a = ((const float4*)(emb + (size_t)grow * D))[c4];
        __nv_bfloat16 h0 = __float2bfloat16(a.x), h1 = __float2bfloat16(a.y);
        __nv_bfloat16 h2 = __float2bfloat16(a.z), h3 = __float2bfloat16(a.w);
        __nv_bfloat16 l0 = __float2bfloat16(a.x - __bfloat162float(h0));
        __nv_bfloat16 l1 = __float2bfloat16(a.y - __bfloat162float(h1));
        __nv_bfloat16 l2 = __float2bfloat16(a.z - __bfloat162float(h2));
        __nv_bfloat16 l3 = __float2bfloat16(a.w - __bfloat162float(h3));
        __nv_bfloat162* ph = (__nv_bfloat162*)(sAh + r * LDA);
        __nv_bfloat162* pl = (__nv_bfloat162*)(sAl + r * LDA);
        ph[c4 * 2]     = __nv_bfloat162(h0, h1);
        ph[c4 * 2 + 1] = __nv_bfloat162(h2, h3);
        pl[c4 * 2]     = __nv_bfloat162(l0, l1);
        pl[c4 * 2 + 1] = __nv_bfloat162(l2, l3);
    }
    __syncthreads();

    wmma::fragment<wmma::accumulator, 16, 16, 16, float> acc[4];
    #pragma unroll
    for (int c = 0; c < 4; c++) wmma::fill_fragment(acc[c], 0.f);

    #pragma unroll
    for (int k = 0; k < 8; k++) {
        wmma::fragment<wmma::matrix_a, 16, 16, 16, __nv_bfloat16, wmma::row_major> ah, al;
        wmma::load_matrix_sync(ah, sAh + wr * 16 * LDA + k * 16, LDA);
        wmma::load_matrix_sync(al, sAl + wr * 16 * LDA + k * 16, LDA);
        #pragma unroll
        for (int c = 0; c < 4; c++) {
            int cc = wc * 64 + c * 16;
            wmma::fragment<wmma::matrix_b, 16, 16, 16, __nv_bfloat16, wmma::row_major> bh, bl;
            wmma::load_matrix_sync(bh, sWh + k * 16 * LDB + cc, LDB);
            wmma::load_matrix_sync(bl, sWl + k * 16 * LDB + cc, LDB);
            wmma::mma_sync(acc[c], ah, bh, acc[c]);
            wmma::mma_sync(acc[c], ah, bl, acc[c]);
            wmma::mma_sync(acc[c], al, bh, acc[c]);
        }
    }
    __syncthreads();
    #pragma unroll
    for (int c = 0; c < 4; c++)
        wmma::store_matrix_sync(sC + wr * 16 * LDC + wc * 64 + c * 16, acc[c],
                                LDC, wmma::mem_row_major);
    __syncthreads();

    for (int i = tid; i < BLK_ROWS * 32; i += 256) {
        int r = i >> 5, c4 = i & 31;
        int grow = block_row + r;
        if (grow < N_NODES) {
            float4 cv = ((const float4*)(sC + r * LDC))[c4];
            float4 bv = ((const float4*)bias)[c4];
            __half2* p = (__half2*)(g_h1h + (size_t)grow * D);
            p[c4 * 2]     = __floats2half2_rn(cv.x + bv.x, cv.y + bv.y);
            p[c4 * 2 + 1] = __floats2half2_rn(cv.z + bv.z, cv.w + bv.w);
        }
    }
}

// ---------------- dual histogram: edges then batch (one atomic pass) ----------------
__global__ void hist_kernel(const int* __restrict__ rows, const int* __restrict__ x) {
    int i = blockIdx.x * blockDim.x + threadIdx.x;
    if (i < N_EDGES) g_eloc[i] = atomicAdd(&g_cnt[rows[i]], 1);
    int b = i - N_EDGES;
    if (b >= 0 && b < BATCH) {
        int xv = x[b];
        if (xv >= 1 && xv <= N_NODES) g_elocb[b] = atomicAdd(&g_cntb[xv - 1], 1);
        else g_elocb[b] = -1;
    }
}

// per-1024-chunk inclusive scan; blockIdx.y selects {edges, batch}
__global__ void scanA_kernel() {
    __shared__ int ws[32];
    int a = blockIdx.y;
    const int* cnt = a ? g_cntb : g_cnt;
    int* rp = a ? g_rowptrb : g_rowptr;
    int* bs = a ? g_bsumB : g_bsumA;
    int tid = threadIdx.x;
    int lane = tid & 31, w = tid >> 5;
    int idx = blockIdx.x * SCAN_CHUNK + tid;
    int v = (idx < N_NODES) ? cnt[idx] : 0;
    int inc = v;
    #pragma unroll
    for (int off = 1; off < 32; off <<= 1) {
        int t = __shfl_up_sync(0xffffffffu, inc, off);
        if (lane >= off) inc += t;
    }
    if (lane == 31) ws[w] = inc;
    __syncthreads();
    if (w == 0) {
        int b = ws[lane];
        #pragma unroll
        for (int off = 1; off < 32; off <<= 1) {
            int t = __shfl_up_sync(0xffffffffu, b, off);
            if (lane >= off) b += t;
        }
        ws[lane] = b;
    }
    __syncthreads();
    int total = inc + (w ? ws[w - 1] : 0);
    if (idx < N_NODES) rp[idx + 1] = total;
    if (tid == SCAN_CHUNK - 1) bs[blockIdx.x] = total;
}

// fused scanB+C: each block reduces the block sums before it, then offsets its chunk
__global__ void scanC_kernel() {
    int a = blockIdx.y;
    int* rp = a ? g_rowptrb : g_rowptr;
    const int* bs = a ? g_bsumB : g_bsumA;
    __shared__ int sacc;
    if (threadIdx.x == 0) sacc = 0;
    __syncthreads();
    int v = (threadIdx.x < blockIdx.x) ? bs[threadIdx.x] : 0;   // blockIdx.x <= 97 < NBLK
    #pragma unroll
    for (int off = 16; off; off >>= 1) v += __shfl_xor_sync(0xffffffffu, v, off);
    if ((threadIdx.x & 31) == 0 && v) atomicAdd(&sacc, v);
    __syncthreads();
    int add = sacc;
    int idx = blockIdx.x * SCAN_CHUNK + threadIdx.x;
    if (idx < N_NODES) rp[idx + 1] += add;
    if (idx == 0) rp[0] = 0;
}

// ---------------- fused scatter: edges + batch ids (+ zero invalid out rows) ----------
__global__ void scatter_kernel(const float* __restrict__ vals,
                               const int* __restrict__ rows,
                               const int* __restrict__ cols,
                               const int* __restrict__ x,
                               float* __restrict__ out) {
    int i = blockIdx.x * blockDim.x + threadIdx.x;
    if (i < N_EDGES) {
        int p = g_rowptr[rows[i]] + g_eloc[i];
        g_epack[p] = make_int2(cols[i], __float_as_int(vals[i]));
    }
    int b = i - N_EDGES;
    if (b >= 0 && b < BATCH) {
        int xv = x[b];
        if (xv >= 1 && xv <= N_NODES) {
            g_bidx[g_rowptrb[xv - 1] + g_elocb[b]] = b;
        } else {
            float4* o = (float4*)(out + (size_t)b * D);
            #pragma unroll
            for (int k = 0; k < 32; k++) o[k] = make_float4(0.f, 0.f, 0.f, 0.f);
        }
    }
}

// ---------------- fused SpMM + ReLU + LayerNorm + direct batch scatter ----------------
// 512 threads = 16 warps/CTA for deeper gather-latency hiding.
__global__ void spmm_ln_kernel(const float* __restrict__ gamma,
                               const float* __restrict__ beta,
                               float* __restrict__ out) {
    int row = blockIdx.x * 16 + (threadIdx.x >> 5);
    if (row >= N_NODES) return;
    int lane = threadIdx.x & 31;
    int s = g_rowptr[row];
    int e = g_rowptr[row + 1];

    float4 acc = make_float4(0.f, 0.f, 0.f, 0.f);
    for (int base = s; base < e; base += 32) {
        int n = min(32, e - base);
        int2 ev = make_int2(0, 0);
        if (base + lane < e) ev = g_epack[base + lane];
        int j = 0;
        for (; j + 8 <= n; j += 8) {
            float v[8]; uint2 m[8];
            #pragma unroll
            for (int u = 0; u < 8; u++) {
                int c = __shfl_sync(0xffffffffu, ev.x, j + u);
                v[u] = __int_as_float(__shfl_sync(0xffffffffu, ev.y, j + u));
                m[u] = ((const uint2*)(g_h1h + (size_t)c * D))[lane];
            }
            #pragma unroll
            for (int u = 0; u < 8; u++) {
                float2 f0 = __half22float2(*(__half2*)&m[u].x);
                float2 f1 = __half22float2(*(__half2*)&m[u].y);
                acc.x = fmaf(v[u], f0.x, acc.x);
                acc.y = fmaf(v[u], f0.y, acc.y);
                acc.z = fmaf(v[u], f1.x, acc.z);
                acc.w = fmaf(v[u], f1.y, acc.w);
            }
        }
        for (; j < n; j++) {
            int   c = __shfl_sync(0xffffffffu, ev.x, j);
            float v = __int_as_float(__shfl_sync(0xffffffffu, ev.y, j));
            uint2 m = ((const uint2*)(g_h1h + (size_t)c * D))[lane];
            float2 f0 = __half22float2(*(__half2*)&m.x);
            float2 f1 = __half22float2(*(__half2*)&m.y);
            acc.x = fmaf(v, f0.x, acc.x);
            acc.y = fmaf(v, f0.y, acc.y);
            acc.z = fmaf(v, f1.x, acc.z);
            acc.w = fmaf(v, f1.y, acc.w);
        }
    }

    acc.x = fmaxf(acc.x, 0.f); acc.y = fmaxf(acc.y, 0.f);
    acc.z = fmaxf(acc.z, 0.f); acc.w = fmaxf(acc.w, 0.f);

    float sm = acc.x + acc.y + acc.z + acc.w;
    #pragma unroll
    for (int o = 16; o; o >>= 1) sm += __shfl_xor_sync(0xffffffffu, sm, o);
    float mu = sm * (1.f / 128.f);

    float dx = acc.x - mu, dy = acc.y - mu, dz = acc.z - mu, dw = acc.w - mu;
    float q = dx * dx + dy * dy + dz * dz + dw * dw;
    #pragma unroll
    for (int o = 16; o; o >>= 1) q += __shfl_xor_sync(0xffffffffu, q, o);
    float rs = rsqrtf(q * (1.f / 128.f) + LN_EPS);

    float4 g = ((const float4*)gamma)[lane];
    float4 b = ((const float4*)beta)[lane];
    float4 o;
    o.x = dx * rs * g.x + b.x;
    o.y = dy * rs * g.y + b.y;
    o.z = dz * rs * g.z + b.z;
    o.w = dw * rs * g.w + b.w;

    int sb = g_rowptrb[row];
    int eb = g_rowptrb[row + 1];
    for (int t = sb; t < eb; t++) {
        int b2 = g_bidx[t];
        __stcs((float4*)(out + (size_t)b2 * D) + lane, o);
    }
}

extern "C" void kernel_launch(void* const* d_in, const int* in_sizes, int n_in,
                              void* d_out, int out_size) {
    const int*   x     = (const int*)d_in[0];
    const float* emb   = (const float*)d_in[1];
    const float* W     = (const float*)d_in[2];
    const float* bias  = (const float*)d_in[3];
    const float* vals  = (const float*)d_in[4];
    const int*   rows  = (const int*)d_in[5];
    const int*   cols  = (const int*)d_in[6];
    const float* gamma = (const float*)d_in[7];
    const float* beta  = (const float*)d_in[8];
    float* out = (float*)d_out;

    cudaFuncSetAttribute(gemm_kernel, cudaFuncAttributeMaxDynamicSharedMemorySize, GEMM_SMEM);

    init_kernel<<<(N_NODES + 255) / 256, 256>>>(W);
    gemm_kernel<<<(N_NODES + BLK_ROWS - 1) / BLK_ROWS, 256, GEMM_SMEM>>>(emb, bias);
    hist_kernel<<<(N_EDGES + BATCH + 255) / 256, 256>>>(rows, x);
    scanA_kernel<<<dim3(NBLK, 2), SCAN_CHUNK>>>();
    scanC_kernel<<<dim3(NBLK, 2), SCAN_CHUNK>>>();
    scatter_kernel<<<(N_EDGES + BATCH + 255) / 256, 256>>>(vals, rows, cols, x, out);
    spmm_ln_kernel<<<(N_NODES + 15) / 16, 512>>>(gamma, beta, out);
}

// round 13
// speedup vs baseline: 1.2445x; 1.0959x over previous
#include <cuda_runtime.h>
#include <cuda_bf16.h>
#include <cuda_fp16.h>
#include <mma.h>

#define N_NODES 100000
#define D 128
#define N_EDGES 1600000
#define BATCH 500000
#define LN_EPS 1e-5f
#define SCAN_CHUNK 1024
#define NBLK ((N_NODES + SCAN_CHUNK - 1) / SCAN_CHUNK)   // 98

using namespace nvcuda;

// Scratch (device globals; no allocation allowed)
__device__ __align__(128) __half g_h1h[N_NODES * D]; // GEMM output (fp16)
__device__ __align__(128) int2  g_epack[N_EDGES];    // CSR-permuted {col, val}
__device__ int g_eloc[N_EDGES];
__device__ int g_elocb[BATCH];
__device__ int g_bidx[BATCH];                        // batch ids grouped by node
__device__ int g_cnt[N_NODES];
__device__ int g_cntb[N_NODES];
__device__ int g_rowptr[N_NODES + 1];
__device__ int g_rowptrb[N_NODES + 1];
__device__ int g_bsumA[NBLK];
__device__ int g_bsumB[NBLK];
__device__ __align__(128) __nv_bfloat16 g_Wh[D * D];
__device__ __align__(128) __nv_bfloat16 g_Wl[D * D];

#define LDA 136
#define LDB 136
#define LDC 132
#define BLK_ROWS 64
#define GEMM_SMEM (128 * LDB * 2 * 2 + BLK_ROWS * LDA * 2 * 2)   // 104448

// ---------------- init: W hi/lo pre-conversion + zero both histograms ----------------
__global__ void init_kernel(const float* __restrict__ W) {
    int i = blockIdx.x * blockDim.x + threadIdx.x;
    if (i < D * D) {
        float wv = W[i];
        __nv_bfloat16 whi = __float2bfloat16(wv);
        g_Wh[i] = whi;
        g_Wl[i] = __float2bfloat16(wv - __bfloat162float(whi));
    }
    if (i < N_NODES) { g_cnt[i] = 0; g_cntb[i] = 0; }
}

// ---------------- GEMM: h1 = emb @ W + bias (bf16 hi/lo, fp32 accum, fp16 store) ------
// W staged in smem via vectorized copy (load-bearing; do not remove).
__global__ void gemm_kernel(const float* __restrict__ emb,
                            const float* __restrict__ bias) {
    extern __shared__ __nv_bfloat16 smem[];
    __nv_bfloat16* sWh = smem;
    __nv_bfloat16* sWl = sWh + 128 * LDB;
    __nv_bfloat16* sAh = sWl + 128 * LDB;
    __nv_bfloat16* sAl = sAh + BLK_ROWS * LDA;
    float* sC = (float*)sAh;

    int tid = threadIdx.x;
    int wid = tid >> 5;
    int wr = wid >> 1;
    int wc = wid & 1;
    int block_row = blockIdx.x * BLK_ROWS;

    for (int i = tid; i < 128 * 16; i += 256) {
        int r = i >> 4, q = i & 15;
        ((uint4*)(sWh + r * LDB))[q] = ((const uint4*)(g_Wh + r * D))[q];
        ((uint4*)(sWl + r * LDB))[q] = ((const uint4*)(g_Wl + r * D))[q];
    }
    for (int i = tid; i < BLK_ROWS * 32; i += 256) {
        int r = i >> 5, c4 = i & 31;
        int grow = block_row + r;
        float4 a = make_float4(0.f, 0.f, 0.f, 0.f);
        if (grow < N_NODES) a = ((const float4*)(emb + (size_t)grow * D))[c4];
        __nv_bfloat16 h0 = __float2bfloat16(a.x), h1 = __float2bfloat16(a.y);
        __nv_bfloat16 h2 = __float2bfloat16(a.z), h3 = __float2bfloat16(a.w);
        __nv_bfloat16 l0 = __float2bfloat16(a.x - __bfloat162float(h0));
        __nv_bfloat16 l1 = __float2bfloat16(a.y - __bfloat162float(h1));
        __nv_bfloat16 l2 = __float2bfloat16(a.z - __bfloat162float(h2));
        __nv_bfloat16 l3 = __float2bfloat16(a.w - __bfloat162float(h3));
        __nv_bfloat162* ph = (__nv_bfloat162*)(sAh + r * LDA);
        __nv_bfloat162* pl = (__nv_bfloat162*)(sAl + r * LDA);
        ph[c4 * 2]     = __nv_bfloat162(h0, h1);
        ph[c4 * 2 + 1] = __nv_bfloat162(h2, h3);
        pl[c4 * 2]     = __nv_bfloat162(l0, l1);
        pl[c4 * 2 + 1] = __nv_bfloat162(l2, l3);
    }
    __syncthreads();

    wmma::fragment<wmma::accumulator, 16, 16, 16, float> acc[4];
    #pragma unroll
    for (int c = 0; c < 4; c++) wmma::fill_fragment(acc[c], 0.f);

    #pragma unroll
    for (int k = 0; k < 8; k++) {
        wmma::fragment<wmma::matrix_a, 16, 16, 16, __nv_bfloat16, wmma::row_major> ah, al;
        wmma::load_matrix_sync(ah, sAh + wr * 16 * LDA + k * 16, LDA);
        wmma::load_matrix_sync(al, sAl + wr * 16 * LDA + k * 16, LDA);
        #pragma unroll
        for (int c = 0; c < 4; c++) {
            int cc = wc * 64 + c * 16;
            wmma::fragment<wmma::matrix_b, 16, 16, 16, __nv_bfloat16, wmma::row_major> bh, bl;
            wmma::load_matrix_sync(bh, sWh + k * 16 * LDB + cc, LDB);
            wmma::load_matrix_sync(bl, sWl + k * 16 * LDB + cc, LDB);
            wmma::mma_sync(acc[c], ah, bh, acc[c]);
            wmma::mma_sync(acc[c], ah, bl, acc[c]);
            wmma::mma_sync(acc[c], al, bh, acc[c]);
        }
    }
    __syncthreads();
    #pragma unroll
    for (int c = 0; c < 4; c++)
        wmma::store_matrix_sync(sC + wr * 16 * LDC + wc * 64 + c * 16, acc[c],
                                LDC, wmma::mem_row_major);
    __syncthreads();

    for (int i = tid; i < BLK_ROWS * 32; i += 256) {
        int r = i >> 5, c4 = i & 31;
        int grow = block_row + r;
        if (grow < N_NODES) {
            float4 cv = ((const float4*)(sC + r * LDC))[c4];
            float4 bv = ((const float4*)bias)[c4];
            __half2* p = (__half2*)(g_h1h + (size_t)grow * D);
            p[c4 * 2]     = __floats2half2_rn(cv.x + bv.x, cv.y + bv.y);
            p[c4 * 2 + 1] = __floats2half2_rn(cv.z + bv.z, cv.w + bv.w);
        }
    }
}

// ---------------- dual histogram: edges then batch (one atomic pass) ----------------
__global__ void hist_kernel(const int* __restrict__ rows, const int* __restrict__ x) {
    int i = blockIdx.x * blockDim.x + threadIdx.x;
    if (i < N_EDGES) g_eloc[i] = atomicAdd(&g_cnt[rows[i]], 1);
    int b = i - N_EDGES;
    if (b >= 0 && b < BATCH) {
        int xv = x[b];
        if (xv >= 1 && xv <= N_NODES) g_elocb[b] = atomicAdd(&g_cntb[xv - 1], 1);
        else g_elocb[b] = -1;
    }
}

// per-1024-chunk inclusive scan; blockIdx.y selects {edges, batch}
__global__ void scanA_kernel() {
    __shared__ int ws[32];
    int a = blockIdx.y;
    const int* cnt = a ? g_cntb : g_cnt;
    int* rp = a ? g_rowptrb : g_rowptr;
    int* bs = a ? g_bsumB : g_bsumA;
    int tid = threadIdx.x;
    int lane = tid & 31, w = tid >> 5;
    int idx = blockIdx.x * SCAN_CHUNK + tid;
    int v = (idx < N_NODES) ? cnt[idx] : 0;
    int inc = v;
    #pragma unroll
    for (int off = 1; off < 32; off <<= 1) {
        int t = __shfl_up_sync(0xffffffffu, inc, off);
        if (lane >= off) inc += t;
    }
    if (lane == 31) ws[w] = inc;
    __syncthreads();
    if (w == 0) {
        int b = ws[lane];
        #pragma unroll
        for (int off = 1; off < 32; off <<= 1) {
            int t = __shfl_up_sync(0xffffffffu, b, off);
            if (lane >= off) b += t;
        }
        ws[lane] = b;
    }
    __syncthreads();
    int total = inc + (w ? ws[w - 1] : 0);
    if (idx < N_NODES) rp[idx + 1] = total;
    if (tid == SCAN_CHUNK - 1) bs[blockIdx.x] = total;
}

// fused scanB+C: each block reduces the block sums before it, then offsets its chunk
__global__ void scanC_kernel() {
    int a = blockIdx.y;
    int* rp = a ? g_rowptrb : g_rowptr;
    const int* bs = a ? g_bsumB : g_bsumA;
    __shared__ int sacc;
    if (threadIdx.x == 0) sacc = 0;
    __syncthreads();
    int v = (threadIdx.x < blockIdx.x) ? bs[threadIdx.x] : 0;   // blockIdx.x <= 97 < NBLK
    #pragma unroll
    for (int off = 16; off; off >>= 1) v += __shfl_xor_sync(0xffffffffu, v, off);
    if ((threadIdx.x & 31) == 0 && v) atomicAdd(&sacc, v);
    __syncthreads();
    int add = sacc;
    int idx = blockIdx.x * SCAN_CHUNK + threadIdx.x;
    if (idx < N_NODES) rp[idx + 1] += add;
    if (idx == 0) rp[0] = 0;
}

// ---------------- fused scatter: edges + batch ids (+ zero invalid out rows) ----------
__global__ void scatter_kernel(const float* __restrict__ vals,
                               const int* __restrict__ rows,
                               const int* __restrict__ cols,
                               const int* __restrict__ x,
                               float* __restrict__ out) {
    int i = blockIdx.x * blockDim.x + threadIdx.x;
    if (i < N_EDGES) {
        int p = g_rowptr[rows[i]] + g_eloc[i];
        g_epack[p] = make_int2(cols[i], __float_as_int(vals[i]));
    }
    int b = i - N_EDGES;
    if (b >= 0 && b < BATCH) {
        int xv = x[b];
        if (xv >= 1 && xv <= N_NODES) {
            g_bidx[g_rowptrb[xv - 1] + g_elocb[b]] = b;
        } else {
            float4* o = (float4*)(out + (size_t)b * D);
            #pragma unroll
            for (int k = 0; k < 32; k++) o[k] = make_float4(0.f, 0.f, 0.f, 0.f);
        }
    }
}

// ---------------- fused SpMM + ReLU + LayerNorm + direct batch scatter ----------------
// R10 config: 256 threads, 8 rows/CTA.
__global__ void spmm_ln_kernel(const float* __restrict__ gamma,
                               const float* __restrict__ beta,
                               float* __restrict__ out) {
    int row = blockIdx.x * 8 + (threadIdx.x >> 5);
    if (row >= N_NODES) return;
    int lane = threadIdx.x & 31;
    int s = g_rowptr[row];
    int e = g_rowptr[row + 1];

    float4 acc = make_float4(0.f, 0.f, 0.f, 0.f);
    for (int base = s; base < e; base += 32) {
        int n = min(32, e - base);
        int2 ev = make_int2(0, 0);
        if (base + lane < e) ev = g_epack[base + lane];
        int j = 0;
        for (; j + 8 <= n; j += 8) {
            float v[8]; uint2 m[8];
            #pragma unroll
            for (int u = 0; u < 8; u++) {
                int c = __shfl_sync(0xffffffffu, ev.x, j + u);
                v[u] = __int_as_float(__shfl_sync(0xffffffffu, ev.y, j + u));
                m[u] = ((const uint2*)(g_h1h + (size_t)c * D))[lane];
            }
            #pragma unroll
            for (int u = 0; u < 8; u++) {
                float2 f0 = __half22float2(*(__half2*)&m[u].x);
                float2 f1 = __half22float2(*(__half2*)&m[u].y);
                acc.x = fmaf(v[u], f0.x, acc.x);
                acc.y = fmaf(v[u], f0.y, acc.y);
                acc.z = fmaf(v[u], f1.x, acc.z);
                acc.w = fmaf(v[u], f1.y, acc.w);
            }
        }
        for (; j < n; j++) {
            int   c = __shfl_sync(0xffffffffu, ev.x, j);
            float v = __int_as_float(__shfl_sync(0xffffffffu, ev.y, j));
            uint2 m = ((const uint2*)(g_h1h + (size_t)c * D))[lane];
            float2 f0 = __half22float2(*(__half2*)&m.x);
            float2 f1 = __half22float2(*(__half2*)&m.y);
            acc.x = fmaf(v, f0.x, acc.x);
            acc.y = fmaf(v, f0.y, acc.y);
            acc.z = fmaf(v, f1.x, acc.z);
            acc.w = fmaf(v, f1.y, acc.w);
        }
    }

    acc.x = fmaxf(acc.x, 0.f); acc.y = fmaxf(acc.y, 0.f);
    acc.z = fmaxf(acc.z, 0.f); acc.w = fmaxf(acc.w, 0.f);

    float sm = acc.x + acc.y + acc.z + acc.w;
    #pragma unroll
    for (int o = 16; o; o >>= 1) sm += __shfl_xor_sync(0xffffffffu, sm, o);
    float mu = sm * (1.f / 128.f);

    float dx = acc.x - mu, dy = acc.y - mu, dz = acc.z - mu, dw = acc.w - mu;
    float q = dx * dx + dy * dy + dz * dz + dw * dw;
    #pragma unroll
    for (int o = 16; o; o >>= 1) q += __shfl_xor_sync(0xffffffffu, q, o);
    float rs = rsqrtf(q * (1.f / 128.f) + LN_EPS);

    float4 g = ((const float4*)gamma)[lane];
    float4 b = ((const float4*)beta)[lane];
    float4 o;
    o.x = dx * rs * g.x + b.x;
    o.y = dy * rs * g.y + b.y;
    o.z = dz * rs * g.z + b.z;
    o.w = dw * rs * g.w + b.w;

    int sb = g_rowptrb[row];
    int eb = g_rowptrb[row + 1];
    for (int t = sb; t < eb; t++) {
        int b2 = g_bidx[t];
        __stcs((float4*)(out + (size_t)b2 * D) + lane, o);
    }
}

extern "C" void kernel_launch(void* const* d_in, const int* in_sizes, int n_in,
                              void* d_out, int out_size) {
    const int*   x     = (const int*)d_in[0];
    const float* emb   = (const float*)d_in[1];
    const float* W     = (const float*)d_in[2];
    const float* bias  = (const float*)d_in[3];
    const float* vals  = (const float*)d_in[4];
    const int*   rows  = (const int*)d_in[5];
    const int*   cols  = (const int*)d_in[6];
    const float* gamma = (const float*)d_in[7];
    const float* beta  = (const float*)d_in[8];
    float* out = (float*)d_out;

    static cudaStream_t s2 = nullptr;
    static cudaEvent_t evFork = nullptr, evJoin = nullptr;
    if (s2 == nullptr) {
        cudaStreamCreateWithFlags(&s2, cudaStreamNonBlocking);
        cudaEventCreateWithFlags(&evFork, cudaEventDisableTiming);
        cudaEventCreateWithFlags(&evJoin, cudaEventDisableTiming);
    }

    cudaFuncSetAttribute(gemm_kernel, cudaFuncAttributeMaxDynamicSharedMemorySize, GEMM_SMEM);

    // init feeds both branches (W for gemm, zeroed counters for hist)
    init_kernel<<<(N_NODES + 255) / 256, 256>>>(W);

    // fork: CSR chain on s2 overlaps GEMM on the main stream
    cudaEventRecord(evFork, 0);
    cudaStreamWaitEvent(s2, evFork, 0);

    hist_kernel<<<(N_EDGES + BATCH + 255) / 256, 256, 0, s2>>>(rows, x);
    scanA_kernel<<<dim3(NBLK, 2), SCAN_CHUNK, 0, s2>>>();
    scanC_kernel<<<dim3(NBLK, 2), SCAN_CHUNK, 0, s2>>>();
    scatter_kernel<<<(N_EDGES + BATCH + 255) / 256, 256, 0, s2>>>(vals, rows, cols, x, out);

    gemm_kernel<<<(N_NODES + BLK_ROWS - 1) / BLK_ROWS, 256, GEMM_SMEM>>>(emb, bias);

    // join
    cudaEventRecord(evJoin, s2);
    cudaStreamWaitEvent(0, evJoin, 0);

    spmm_ln_kernel<<<(N_NODES + 7) / 8, 256>>>(gamma, beta, out);
}